// round 7
// baseline (speedup 1.0000x reference)
#include <cuda_runtime.h>
#include <cstdint>

// ============================================================================
// LSTM cell, B=16384, IN=H=1024, fp32.  Target: compute_103 baseline ISA
// (NO 'a' features: no tcgen05, no TMA multicast). Ampere-style pipeline:
//   mma.sync.m16n8k8 tf32 + ldmatrix + cp.async 3-stage.
// Fused GEMM: A[16384,2048] (X||prev_h, rna-tf32 packed) x Wt[4096,2048]
// CTA tile M=256 x N=128 (4 gates x 32 cols) x K=32; LSTM epilogue in-kernel.
// ============================================================================

#define B_DIM  16384
#define H_DIM  1024
#define K_TOT  2048
#define CTA_M  256
#define CTA_N  128
#define CTA_K  32
#define ITERS  (K_TOT / CTA_K)          // 64
#define STAGES 3

#define A_STRIDE 36                      // floats per smem row (pad: 4r+c banks)
#define A_TILE_F (CTA_M * A_STRIDE)      // 9216 floats
#define B_TILE_F (CTA_N * A_STRIDE)      // 4608 floats
#define STAGE_F  (A_TILE_F + B_TILE_F)   // 13824 floats
#define SMEM_BYTES (STAGES * STAGE_F * 4)  // 165888 B
#define EPI_STRIDE 132                   // epilogue exchange pitch (135168 B)

// Scratch (static __device__ = allowed): rna-tf32-converted operands
__device__ float g_Wt[4096ull * 2048ull];          // [g*1024+n][k]
__device__ float g_A[(size_t)B_DIM * K_TOT];       // [m][k]  (X || prev_h)

// ---------------------------------------------------------------------------
__device__ __forceinline__ uint32_t smem_u32(const void* p) {
    uint32_t a;
    asm("{ .reg .u64 t; cvta.to.shared.u64 t, %1; cvt.u32.u64 %0, t; }"
        : "=r"(a) : "l"(p));
    return a;
}
__device__ __forceinline__ float to_tf32(float x) {
    float y;
    asm("cvt.rna.tf32.f32 %0, %1;" : "=f"(y) : "f"(x));
    return y;
}
__device__ __forceinline__ void cp16(uint32_t dst, const void* src) {
    asm volatile("cp.async.cg.shared.global [%0], [%1], 16;"
                 :: "r"(dst), "l"(src));
}
__device__ __forceinline__ void cp_commit() {
    asm volatile("cp.async.commit_group;");
}
__device__ __forceinline__ void ldsm_x4(uint32_t* r, uint32_t addr) {
    asm volatile("ldmatrix.sync.aligned.m8n8.x4.shared.b16 {%0,%1,%2,%3}, [%4];"
                 : "=r"(r[0]), "=r"(r[1]), "=r"(r[2]), "=r"(r[3]) : "r"(addr));
}
__device__ __forceinline__ void ldsm_x2(uint32_t* r, uint32_t addr) {
    asm volatile("ldmatrix.sync.aligned.m8n8.x2.shared.b16 {%0,%1}, [%2];"
                 : "=r"(r[0]), "=r"(r[1]) : "r"(addr));
}
__device__ __forceinline__ void mma_tf32(float* d, const uint32_t* a,
                                         const uint32_t* b) {
    asm volatile(
        "mma.sync.aligned.m16n8k8.row.col.f32.tf32.tf32.f32 "
        "{%0,%1,%2,%3}, {%4,%5,%6,%7}, {%8,%9}, {%0,%1,%2,%3};"
        : "+f"(d[0]), "+f"(d[1]), "+f"(d[2]), "+f"(d[3])
        : "r"(a[0]), "r"(a[1]), "r"(a[2]), "r"(a[3]), "r"(b[0]), "r"(b[1]));
}
__device__ __forceinline__ float fsigmoid(float x) {
    return 1.0f / (1.0f + __expf(-x));
}

// ---------------------------------------------------------------------------
// Prologue 1: pack X||prev_h into g_A with rna-tf32 conversion.
// ---------------------------------------------------------------------------
__global__ void pack_a_kernel(const float* __restrict__ x,
                              const float* __restrict__ h) {
    size_t idx4 = (size_t)blockIdx.x * 256 + threadIdx.x;  // float4 index
    int m = (int)(idx4 >> 9);            // 512 float4 per 2048-row
    int k = ((int)idx4 & 511) * 4;
    const float* src = (k < 1024) ? x + (size_t)m * 1024 + k
                                  : h + (size_t)m * 1024 + (k - 1024);
    float4 v = *(const float4*)src;
    v.x = to_tf32(v.x); v.y = to_tf32(v.y);
    v.z = to_tf32(v.z); v.w = to_tf32(v.w);
    *(float4*)(g_A + (size_t)m * K_TOT + k) = v;
}

// ---------------------------------------------------------------------------
// Prologue 2: transpose 8x [1024,1024] W into g_Wt[(g*1024+n)][k], rna-tf32.
// gate order i,f,u,o; part 0 = x-weights (k 0..1023), 1 = h-weights.
// ---------------------------------------------------------------------------
struct WPtrs { const float* p[8]; };

__global__ void wt_transpose_kernel(WPtrs w) {
    __shared__ float t[32][33];
    int z = blockIdx.z;                  // 0..7 = g*2 + part
    const float* src = w.p[z];
    int g = z >> 1, part = z & 1;
    int n = blockIdx.x * 32 + threadIdx.x;
    int kb = blockIdx.y * 32;
#pragma unroll
    for (int j = 0; j < 32; j += 8)
        t[threadIdx.y + j][threadIdx.x] =
            src[(size_t)(kb + threadIdx.y + j) * 1024 + n];
    __syncthreads();
    int nn = blockIdx.x * 32 + threadIdx.y;
    int kk = kb + threadIdx.x;
#pragma unroll
    for (int j = 0; j < 32; j += 8)
        g_Wt[(size_t)(g * 1024 + nn + j) * K_TOT + part * 1024 + kk] =
            to_tf32(t[threadIdx.x][threadIdx.y + j]);
}

// ---------------------------------------------------------------------------
// Main fused kernel: 256 threads, 8 warps (4 M x 2 N), warp tile 64x64.
// ---------------------------------------------------------------------------
__global__ void __launch_bounds__(256, 1) lstm_mma_kernel(
    const float* __restrict__ prev_c,
    const float* __restrict__ bias_i, const float* __restrict__ bias_f,
    const float* __restrict__ bias_o, const float* __restrict__ bias_u,
    float* __restrict__ out) {
    extern __shared__ float smem[];
    const uint32_t sb = smem_u32(smem);
    const int tid = threadIdx.x;
    const int wid = tid >> 5, lane = tid & 31;
    const int warp_m = wid >> 1, warp_n = wid & 1;
    // n-fastest grid: W stays hot in L2, A tiles read from DRAM once.
    const int ntile = blockIdx.x & 31;           // 32 col-tiles
    const int mtile = blockIdx.x >> 5;           // 64 m-tiles
    const int m0 = mtile * CTA_M;
    const int n0c = ntile * 32;                  // per-gate col base

    float acc[4][8][4];
#pragma unroll
    for (int i = 0; i < 4; i++)
#pragma unroll
        for (int j = 0; j < 8; j++)
#pragma unroll
            for (int r = 0; r < 4; r++) acc[i][j][r] = 0.0f;

    // ldmatrix per-lane row/col selectors
    const int quad = lane >> 3;
    const int rselA = (lane & 7) + ((quad & 1) << 3);
    const int cselA = (quad >> 1) << 2;
    const int lsel = lane & 15;
    const int rselB = lsel & 7;
    const int cselB = ((lsel >> 3) & 1) << 2;

    // stage loader: A 2048 float4, B 1024 float4
    auto load_stage = [&](int s, int ci) {
        const int k0 = ci * CTA_K;
        const uint32_t As = sb + (uint32_t)(s * STAGE_F) * 4;
        const uint32_t Bs = As + A_TILE_F * 4;
#pragma unroll
        for (int i = 0; i < 8; i++) {
            int idx = tid + i * 256;
            int row = idx >> 3, q = idx & 7;
            cp16(As + (uint32_t)(row * A_STRIDE + q * 4) * 4,
                 g_A + (size_t)(m0 + row) * K_TOT + k0 + q * 4);
        }
#pragma unroll
        for (int i = 0; i < 4; i++) {
            int idx = tid + i * 256;
            int row = idx >> 3, q = idx & 7;
            int nglob = (row >> 5) * 1024 + n0c + (row & 31);
            cp16(Bs + (uint32_t)(row * A_STRIDE + q * 4) * 4,
                 g_Wt + (size_t)nglob * K_TOT + k0 + q * 4);
        }
    };

    load_stage(0, 0); cp_commit();
    load_stage(1, 1); cp_commit();

    for (int ci = 0; ci < ITERS; ci++) {
        if (ci < ITERS - 1)
            asm volatile("cp.async.wait_group 1;" ::: "memory");
        else
            asm volatile("cp.async.wait_group 0;" ::: "memory");
        __syncthreads();
        if (ci + 2 < ITERS) { load_stage((ci + 2) % STAGES, ci + 2); cp_commit(); }

        const int s = ci % STAGES;
        const uint32_t As = sb + (uint32_t)(s * STAGE_F) * 4;
        const uint32_t Bs = As + A_TILE_F * 4;
#pragma unroll
        for (int ks = 0; ks < 4; ks++) {
            uint32_t a[4][4], b[8][2];
#pragma unroll
            for (int mt = 0; mt < 4; mt++)
                ldsm_x4(a[mt], As + (uint32_t)((warp_m * 64 + mt * 16 + rselA) *
                                               A_STRIDE + ks * 8 + cselA) * 4);
#pragma unroll
            for (int nt = 0; nt < 8; nt++)
                ldsm_x2(b[nt], Bs + (uint32_t)((warp_n * 64 + nt * 8 + rselB) *
                                               A_STRIDE + ks * 8 + cselB) * 4);
#pragma unroll
            for (int mt = 0; mt < 4; mt++)
#pragma unroll
                for (int nt = 0; nt < 8; nt++)
                    mma_tf32(acc[mt][nt], a[mt], b[nt]);
        }
    }

    // ---- epilogue: exchange accums through smem, finish LSTM ----
    __syncthreads();                    // all warps done reading pipeline smem
    float* epi = smem;                  // 256 x 132 fp32
#pragma unroll
    for (int mt = 0; mt < 4; mt++)
#pragma unroll
        for (int nt = 0; nt < 8; nt++) {
            int row = warp_m * 64 + mt * 16 + (lane >> 2);
            int col = warp_n * 64 + nt * 8 + 2 * (lane & 3);
            *(float2*)&epi[row * EPI_STRIDE + col] =
                make_float2(acc[mt][nt][0], acc[mt][nt][1]);
            *(float2*)&epi[(row + 8) * EPI_STRIDE + col] =
                make_float2(acc[mt][nt][2], acc[mt][nt][3]);
        }
    __syncthreads();

    const int colL = tid & 31;
    const float bi = bias_i[n0c + colL];
    const float bf = bias_f[n0c + colL];
    const float bu = bias_u[n0c + colL];
    const float bo = bias_o[n0c + colL];
    const size_t BH = (size_t)B_DIM * H_DIM;
#pragma unroll 4
    for (int i = 0; i < 32; i++) {
        int mL = (tid >> 5) + i * 8;
        const float* row = epi + mL * EPI_STRIDE;
        float zi = row[colL] + bi;            // gate order i,f,u,o (32 each)
        float zf = row[32 + colL] + bf;
        float zu = row[64 + colL] + bu;
        float zo = row[96 + colL] + bo;
        size_t off = (size_t)(m0 + mL) * H_DIM + n0c + colL;
        float cp = prev_c[off];
        float cc = fsigmoid(zf) * cp + fsigmoid(zi) * tanhf(zu);
        out[off] = fsigmoid(zo) * tanhf(cc);  // h
        out[BH + off] = cc;                   // c
    }
}

// ---------------------------------------------------------------------------
extern "C" void kernel_launch(void* const* d_in, const int* in_sizes, int n_in,
                              void* d_out, int out_size) {
    const float* input  = (const float*)d_in[0];
    const float* prev_h = (const float*)d_in[1];
    const float* prev_c = (const float*)d_in[2];
    WPtrs w;
    w.p[0] = (const float*)d_in[3];  // weight_xi
    w.p[1] = (const float*)d_in[4];  // weight_hi
    w.p[2] = (const float*)d_in[5];  // weight_xf
    w.p[3] = (const float*)d_in[6];  // weight_hf
    w.p[4] = (const float*)d_in[7];  // weight_xu
    w.p[5] = (const float*)d_in[8];  // weight_hu
    w.p[6] = (const float*)d_in[9];  // weight_xo
    w.p[7] = (const float*)d_in[10]; // weight_ho
    const float* bias_i = (const float*)d_in[11];
    const float* bias_f = (const float*)d_in[12];
    const float* bias_o = (const float*)d_in[13];
    const float* bias_u = (const float*)d_in[14];

    // Prologues (every call; deterministic, no caching)
    pack_a_kernel<<<(B_DIM * (K_TOT / 4)) / 256, 256>>>(input, prev_h);
    wt_transpose_kernel<<<dim3(32, 32, 8), dim3(32, 8)>>>(w);

    cudaFuncSetAttribute(lstm_mma_kernel,
                         cudaFuncAttributeMaxDynamicSharedMemorySize,
                         SMEM_BYTES);
    lstm_mma_kernel<<<(B_DIM / CTA_M) * 32, 256, SMEM_BYTES>>>(
        prev_c, bias_i, bias_f, bias_o, bias_u, (float*)d_out);
}

// round 8
// speedup vs baseline: 1.4771x; 1.4771x over previous
#include <cuda_runtime.h>
#include <cuda_fp16.h>
#include <cstdint>

// ============================================================================
// LSTM cell, B=16384, IN=H=1024, fp32.  Target: compute_103 baseline ISA.
// fp16 (same 10-bit mantissa as tf32) mma.sync.m16n8k16 + ldmatrix +
// 3-stage cp.async. Fused GEMM A[16384,2048] x Wt[4096,2048] + LSTM epilogue.
// CTA tile M=256 x N=128 (4 gates x 32 cols) x K=32.
// ============================================================================

#define B_DIM  16384
#define H_DIM  1024
#define K_TOT  2048
#define CTA_M  256
#define CTA_N  128
#define CTA_K  32
#define ITERS  (K_TOT / CTA_K)          // 64
#define STAGES 3

#define PITCH    40                      // halves per smem row (80 B: 20m mod 32
                                         // covers all 8 4-bank segs -> no conflicts)
#define A_TILE_H (CTA_M * PITCH)         // 10240 halves
#define B_TILE_H (CTA_N * PITCH)         // 5120 halves
#define STAGE_B  ((A_TILE_H + B_TILE_H) * 2)   // 30720 B
#define EPI_STRIDE 132
#define SMEM_BYTES (CTA_M * EPI_STRIDE * 4)    // 135168 B (> 3*STAGE_B = 92160)

// Scratch: fp16-converted operands
__device__ __half g_Wt[4096ull * 2048ull];         // [g*1024+n][k]  16 MB
__device__ __half g_A[(size_t)B_DIM * K_TOT];      // [m][k] X||prev_h  64 MB

// ---------------------------------------------------------------------------
__device__ __forceinline__ uint32_t smem_u32(const void* p) {
    uint32_t a;
    asm("{ .reg .u64 t; cvta.to.shared.u64 t, %1; cvt.u32.u64 %0, t; }"
        : "=r"(a) : "l"(p));
    return a;
}
__device__ __forceinline__ void cp16(uint32_t dst, const void* src) {
    asm volatile("cp.async.cg.shared.global [%0], [%1], 16;"
                 :: "r"(dst), "l"(src));
}
__device__ __forceinline__ void cp_commit() {
    asm volatile("cp.async.commit_group;");
}
__device__ __forceinline__ void ldsm_x4(uint32_t* r, uint32_t addr) {
    asm volatile("ldmatrix.sync.aligned.m8n8.x4.shared.b16 {%0,%1,%2,%3}, [%4];"
                 : "=r"(r[0]), "=r"(r[1]), "=r"(r[2]), "=r"(r[3]) : "r"(addr));
}
__device__ __forceinline__ void ldsm_x2(uint32_t* r, uint32_t addr) {
    asm volatile("ldmatrix.sync.aligned.m8n8.x2.shared.b16 {%0,%1}, [%2];"
                 : "=r"(r[0]), "=r"(r[1]) : "r"(addr));
}
__device__ __forceinline__ void mma_f16(float* d, const uint32_t* a,
                                        const uint32_t* b) {
    asm volatile(
        "mma.sync.aligned.m16n8k16.row.col.f32.f16.f16.f32 "
        "{%0,%1,%2,%3}, {%4,%5,%6,%7}, {%8,%9}, {%0,%1,%2,%3};"
        : "+f"(d[0]), "+f"(d[1]), "+f"(d[2]), "+f"(d[3])
        : "r"(a[0]), "r"(a[1]), "r"(a[2]), "r"(a[3]), "r"(b[0]), "r"(b[1]));
}
__device__ __forceinline__ float fsigmoid(float x) {
    return 1.0f / (1.0f + __expf(-x));
}

// ---------------------------------------------------------------------------
// Prologue 1: pack X||prev_h into g_A (fp16, rn).
// ---------------------------------------------------------------------------
__global__ void pack_a_kernel(const float* __restrict__ x,
                              const float* __restrict__ h) {
    size_t idx4 = (size_t)blockIdx.x * 256 + threadIdx.x;  // float4 index
    int m = (int)(idx4 >> 9);
    int k = ((int)idx4 & 511) * 4;
    const float* src = (k < 1024) ? x + (size_t)m * 1024 + k
                                  : h + (size_t)m * 1024 + (k - 1024);
    float4 v = *(const float4*)src;
    __half2 h2[2];
    h2[0] = __floats2half2_rn(v.x, v.y);
    h2[1] = __floats2half2_rn(v.z, v.w);
    *(uint2*)(g_A + (size_t)m * K_TOT + k) = *(const uint2*)h2;
}

// ---------------------------------------------------------------------------
// Prologue 2: transpose 8x [1024,1024] W -> g_Wt[(g*1024+n)][k], fp16.
// gate order i,f,u,o; part 0 = x-weights (k 0..1023), 1 = h-weights.
// ---------------------------------------------------------------------------
struct WPtrs { const float* p[8]; };

__global__ void wt_transpose_kernel(WPtrs w) {
    __shared__ float t[32][33];
    int z = blockIdx.z;                  // 0..7 = g*2 + part
    const float* src = w.p[z];
    int g = z >> 1, part = z & 1;
    int n = blockIdx.x * 32 + threadIdx.x;
    int kb = blockIdx.y * 32;
#pragma unroll
    for (int j = 0; j < 32; j += 8)
        t[threadIdx.y + j][threadIdx.x] =
            src[(size_t)(kb + threadIdx.y + j) * 1024 + n];
    __syncthreads();
    int nn = blockIdx.x * 32 + threadIdx.y;
    int kk = kb + threadIdx.x;
#pragma unroll
    for (int j = 0; j < 32; j += 8)
        g_Wt[(size_t)(g * 1024 + nn + j) * K_TOT + part * 1024 + kk] =
            __float2half_rn(t[threadIdx.x][threadIdx.y + j]);
}

// ---------------------------------------------------------------------------
// Main fused kernel: 256 threads, 8 warps (4 M x 2 N), warp tile 64x64.
// ---------------------------------------------------------------------------
__global__ void __launch_bounds__(256, 1) lstm_mma_kernel(
    const float* __restrict__ prev_c,
    const float* __restrict__ bias_i, const float* __restrict__ bias_f,
    const float* __restrict__ bias_o, const float* __restrict__ bias_u,
    float* __restrict__ out) {
    extern __shared__ float smem[];
    const uint32_t sb = smem_u32(smem);
    const int tid = threadIdx.x;
    const int wid = tid >> 5, lane = tid & 31;
    const int warp_m = wid >> 1, warp_n = wid & 1;
    // n-fastest grid: W stays hot in L2, each A tile read from DRAM once.
    const int ntile = blockIdx.x & 31;
    const int mtile = blockIdx.x >> 5;
    const int m0 = mtile * CTA_M;
    const int n0c = ntile * 32;              // per-gate col base

    float acc[4][8][4];
#pragma unroll
    for (int i = 0; i < 4; i++)
#pragma unroll
        for (int j = 0; j < 8; j++)
#pragma unroll
            for (int r = 0; r < 4; r++) acc[i][j][r] = 0.0f;

    // ldmatrix lane selectors
    const int rselA = lane & 15;             // m within 16
    const int cselA = (lane >> 4) << 3;      // k half-group (0 / 8)
    const int rselB = lane & 7;              // n within 8
    const int cselB = ((lane >> 3) & 1) << 3;  // k half-group (0 / 8)

    // stage loader: A 1024 cp16, B 512 cp16 (16 B each)
    auto load_stage = [&](int s, int ci) {
        const int k0 = ci * CTA_K;
        const uint32_t As = sb + (uint32_t)s * STAGE_B;
        const uint32_t Bs = As + A_TILE_H * 2;
#pragma unroll
        for (int i = 0; i < 4; i++) {         // A: 256 rows x 4 segs
            int idx = tid + i * 256;
            int row = idx >> 2, seg = idx & 3;
            cp16(As + (uint32_t)(row * PITCH + seg * 8) * 2,
                 g_A + (size_t)(m0 + row) * K_TOT + k0 + seg * 8);
        }
#pragma unroll
        for (int i = 0; i < 2; i++) {         // B: 128 rows x 4 segs
            int idx = tid + i * 256;
            int row = idx >> 2, seg = idx & 3;
            int nglob = (row >> 5) * 1024 + n0c + (row & 31);
            cp16(Bs + (uint32_t)(row * PITCH + seg * 8) * 2,
                 g_Wt + (size_t)nglob * K_TOT + k0 + seg * 8);
        }
    };

    load_stage(0, 0); cp_commit();
    load_stage(1, 1); cp_commit();

    for (int ci = 0; ci < ITERS; ci++) {
        if (ci < ITERS - 1)
            asm volatile("cp.async.wait_group 1;" ::: "memory");
        else
            asm volatile("cp.async.wait_group 0;" ::: "memory");
        __syncthreads();
        if (ci + 2 < ITERS) { load_stage((ci + 2) % STAGES, ci + 2); cp_commit(); }

        const int s = ci % STAGES;
        const uint32_t As = sb + (uint32_t)s * STAGE_B;
        const uint32_t Bs = As + A_TILE_H * 2;
#pragma unroll
        for (int ks = 0; ks < 2; ks++) {      // 2 x k16 per 32-chunk
            uint32_t a[4][4], b[8][2];
#pragma unroll
            for (int mt = 0; mt < 4; mt++)
                ldsm_x4(a[mt], As + (uint32_t)((warp_m * 64 + mt * 16 + rselA) *
                                               PITCH + ks * 16 + cselA) * 2);
#pragma unroll
            for (int nt = 0; nt < 8; nt++)
                ldsm_x2(b[nt], Bs + (uint32_t)((warp_n * 64 + nt * 8 + rselB) *
                                               PITCH + ks * 16 + cselB) * 2);
#pragma unroll
            for (int mt = 0; mt < 4; mt++)
#pragma unroll
                for (int nt = 0; nt < 8; nt++)
                    mma_f16(acc[mt][nt], a[mt], b[nt]);
        }
    }

    // ---- epilogue: exchange accums through smem, finish LSTM ----
    __syncthreads();
    float* epi = smem;                       // 256 x 132 fp32
#pragma unroll
    for (int mt = 0; mt < 4; mt++)
#pragma unroll
        for (int nt = 0; nt < 8; nt++) {
            int row = warp_m * 64 + mt * 16 + (lane >> 2);
            int col = warp_n * 64 + nt * 8 + 2 * (lane & 3);
            *(float2*)&epi[row * EPI_STRIDE + col] =
                make_float2(acc[mt][nt][0], acc[mt][nt][1]);
            *(float2*)&epi[(row + 8) * EPI_STRIDE + col] =
                make_float2(acc[mt][nt][2], acc[mt][nt][3]);
        }
    __syncthreads();

    const int colL = tid & 31;
    const float bi = bias_i[n0c + colL];
    const float bf = bias_f[n0c + colL];
    const float bu = bias_u[n0c + colL];
    const float bo = bias_o[n0c + colL];
    const size_t BH = (size_t)B_DIM * H_DIM;
#pragma unroll 4
    for (int i = 0; i < 32; i++) {
        int mL = (tid >> 5) + i * 8;
        const float* row = epi + mL * EPI_STRIDE;
        float zi = row[colL] + bi;           // gate order i,f,u,o (32 each)
        float zf = row[32 + colL] + bf;
        float zu = row[64 + colL] + bu;
        float zo = row[96 + colL] + bo;
        size_t off = (size_t)(m0 + mL) * H_DIM + n0c + colL;
        float cp = prev_c[off];
        float cc = fsigmoid(zf) * cp + fsigmoid(zi) * tanhf(zu);
        out[off] = fsigmoid(zo) * tanhf(cc); // h
        out[BH + off] = cc;                  // c
    }
}

// ---------------------------------------------------------------------------
extern "C" void kernel_launch(void* const* d_in, const int* in_sizes, int n_in,
                              void* d_out, int out_size) {
    const float* input  = (const float*)d_in[0];
    const float* prev_h = (const float*)d_in[1];
    const float* prev_c = (const float*)d_in[2];
    WPtrs w;
    w.p[0] = (const float*)d_in[3];  // weight_xi
    w.p[1] = (const float*)d_in[4];  // weight_hi
    w.p[2] = (const float*)d_in[5];  // weight_xf
    w.p[3] = (const float*)d_in[6];  // weight_hf
    w.p[4] = (const float*)d_in[7];  // weight_xu
    w.p[5] = (const float*)d_in[8];  // weight_hu
    w.p[6] = (const float*)d_in[9];  // weight_xo
    w.p[7] = (const float*)d_in[10]; // weight_ho
    const float* bias_i = (const float*)d_in[11];
    const float* bias_f = (const float*)d_in[12];
    const float* bias_o = (const float*)d_in[13];
    const float* bias_u = (const float*)d_in[14];

    pack_a_kernel<<<(B_DIM * (K_TOT / 4)) / 256, 256>>>(input, prev_h);
    wt_transpose_kernel<<<dim3(32, 32, 8), dim3(32, 8)>>>(w);

    cudaFuncSetAttribute(lstm_mma_kernel,
                         cudaFuncAttributeMaxDynamicSharedMemorySize,
                         SMEM_BYTES);
    lstm_mma_kernel<<<(B_DIM / CTA_M) * 32, 256, SMEM_BYTES>>>(
        prev_c, bias_i, bias_f, bias_o, bias_u, (float*)d_out);
}